// round 6
// baseline (speedup 1.0000x reference)
#include <cuda_runtime.h>

#define NTH  256
typedef unsigned long long u64;

struct Params { const float* p[27]; };

// ---------- packed f32x2 primitives (sm_103a) ----------
__device__ __forceinline__ u64 ffma2(u64 a, u64 b, u64 c) {
    u64 d; asm("fma.rn.f32x2 %0,%1,%2,%3;" : "=l"(d) : "l"(a), "l"(b), "l"(c)); return d;
}
__device__ __forceinline__ u64 fmul2(u64 a, u64 b) {
    u64 d; asm("mul.rn.f32x2 %0,%1,%2;" : "=l"(d) : "l"(a), "l"(b)); return d;
}
__device__ __forceinline__ u64 fadd2(u64 a, u64 b) {
    u64 d; asm("add.rn.f32x2 %0,%1,%2;" : "=l"(d) : "l"(a), "l"(b)); return d;
}
__device__ __forceinline__ u64 pack2(float lo, float hi) {
    u64 d; asm("mov.b64 %0,{%1,%2};" : "=l"(d) : "f"(lo), "f"(hi)); return d;
}
__device__ __forceinline__ void unpack2(u64 v, float& lo, float& hi) {
    asm("mov.b64 {%0,%1},%2;" : "=f"(lo), "=f"(hi) : "l"(v));
}
__device__ __forceinline__ u64 abs2(u64 v) {
    u64 d; asm("and.b64 %0,%1,0x7FFFFFFF7FFFFFFF;" : "=l"(d) : "l"(v)); return d;
}
// Packed branchless leaky-relu (slope 0.0025): rr(v) = 0.50125*v + 0.49875*|v|.
// abs2 -> alu pipe; fmul2+ffma2 -> fma pipe (1 fma-op per value).
__device__ __forceinline__ u64 rr2(u64 v) {
    const u64 C1 = pack2(0.50125f, 0.50125f);
    const u64 C2 = pack2(0.49875f, 0.49875f);
    return ffma2(v, C1, fmul2(abs2(v), C2));
}

// ---------- shared weight offsets (u64 slots, each scalar duplicated) ----------
#define O_W_IN   0
#define O_B_IN   64
#define O_W_H1   72
#define O_B_H1   104
#define O_W_H2   108
#define O_B_H2   124
#define O_W_H3   128
#define O_B_H3   144
#define O_W_H4   148
#define O_B_H4   164
#define O_W_H5   168
#define O_B_H5   184
#define O_W_EN   188
#define O_B_EN   192
#define O_W_H6   193
#define O_B_H6   197
#define O_W_H7   201
#define O_B_H7   217
#define O_W_H8   221
#define O_B_H8   237
#define O_W_H9   241
#define O_B_H9   257
#define O_W_HA   261
#define O_B_HA   277
#define O_W_DE   281
#define O_B_DE   313
#define S_TOTAL  321

// dst[p][j] = (ACT? rr2:id)( {b,b} + sum_i src[p][i]*{w,w} ), 2 row-pairs
template<int FI, int FO, bool ACT>
__device__ __forceinline__ void lin(const u64* __restrict__ s, int Woff, int boff,
                                    const u64 (&src)[2][FI], u64 (&dst)[2][FO]) {
#pragma unroll
    for (int j = 0; j < FO; j++) {
        u64 b = s[boff + j];
        u64 a0 = b, a1 = b;
#pragma unroll
        for (int i = 0; i < FI; i++) {
            u64 w = s[Woff + i * FO + j];       // one LDS.64 feeds both pairs
            a0 = ffma2(src[0][i], w, a0);
            a1 = ffma2(src[1][i], w, a1);
        }
        dst[0][j] = ACT ? rr2(a0) : a0;
        dst[1][j] = ACT ? rr2(a1) : a1;
    }
}

// dst[p][j] += {b,b} + sum_i src[p][i]*{w,w}   (residual, no activation)
template<int FI, int FO>
__device__ __forceinline__ void lin_add(const u64* __restrict__ s, int Woff, int boff,
                                        const u64 (&src)[2][FI], u64 (&dst)[2][FO]) {
#pragma unroll
    for (int j = 0; j < FO; j++) {
        u64 b = s[boff + j];
        u64 a0 = b, a1 = b;
#pragma unroll
        for (int i = 0; i < FI; i++) {
            u64 w = s[Woff + i * FO + j];
            a0 = ffma2(src[0][i], w, a0);
            a1 = ffma2(src[1][i], w, a1);
        }
        dst[0][j] = fadd2(dst[0][j], a0);
        dst[1][j] = fadd2(dst[1][j], a1);
    }
}

__global__ __launch_bounds__(NTH, 4)
void ann_fused_kernel(Params P, float* __restrict__ out, int N) {
    __shared__ u64 s[S_TOTAL];

    // Cooperative weight load: duplicate each scalar into both f32x2 lanes.
    {
        const int sz[26] = {64,8,32,4,16,4,16,4,16,4,16,4,4,1,4,4,16,4,16,4,16,4,16,4,32,8};
        int off = 0;
        for (int k = 0; k < 26; k++) {
            const float* src = P.p[k + 1];
            for (int i = threadIdx.x; i < sz[k]; i += NTH) {
                float v = src[i];
                s[off + i] = pack2(v, v);
            }
            off += sz[k];
        }
    }
    __syncthreads();

    const float* __restrict__ xin = P.p[0];
    unsigned base = blockIdx.x * (4 * NTH) + threadIdx.x;
    // pair p covers rows (base + 2p*NTH, base + (2p+1)*NTH)

    // ---- load x_in, pack 2 rows per u64 lane-pair (streaming float4 loads) ----
    u64 x8[2][8];
#pragma unroll
    for (int p = 0; p < 2; p++) {
        unsigned rA = base + (2 * p) * NTH;
        unsigned rB = rA + NTH;
        float4 a0, a1, b0, b1;
        if (rA < (unsigned)N) {
            a0 = __ldcs(reinterpret_cast<const float4*>(xin + (size_t)rA * 8));
            a1 = __ldcs(reinterpret_cast<const float4*>(xin + (size_t)rA * 8 + 4));
        } else { a0 = a1 = make_float4(0.f,0.f,0.f,0.f); }
        if (rB < (unsigned)N) {
            b0 = __ldcs(reinterpret_cast<const float4*>(xin + (size_t)rB * 8));
            b1 = __ldcs(reinterpret_cast<const float4*>(xin + (size_t)rB * 8 + 4));
        } else { b0 = b1 = make_float4(0.f,0.f,0.f,0.f); }
        x8[p][0] = pack2(a0.x, b0.x); x8[p][1] = pack2(a0.y, b0.y);
        x8[p][2] = pack2(a0.z, b0.z); x8[p][3] = pack2(a0.w, b0.w);
        x8[p][4] = pack2(a1.x, b1.x); x8[p][5] = pack2(a1.y, b1.y);
        x8[p][6] = pack2(a1.z, b1.z); x8[p][7] = pack2(a1.w, b1.w);
    }

    // ---- fused in+h1 (column-wise, keeps liveness low):
    //   x4 = rr(x8 @ W_in + b_in) @ W_h1 + b_h1
    u64 x[2][4], t[2][4];
#pragma unroll
    for (int k = 0; k < 4; k++) { u64 b = s[O_B_H1 + k]; x[0][k] = b; x[1][k] = b; }
#pragma unroll
    for (int j = 0; j < 8; j++) {
        u64 b = s[O_B_IN + j];
        u64 a0 = b, a1 = b;
#pragma unroll
        for (int i = 0; i < 8; i++) {
            u64 w = s[O_W_IN + i * 8 + j];
            a0 = ffma2(x8[0][i], w, a0);
            a1 = ffma2(x8[1][i], w, a1);
        }
        a0 = rr2(a0); a1 = rr2(a1);
#pragma unroll
        for (int k = 0; k < 4; k++) {
            u64 w = s[O_W_H1 + j * 4 + k];
            x[0][k] = ffma2(a0, w, x[0][k]);
            x[1][k] = ffma2(a1, w, x[1][k]);
        }
    }
    // x8 dead from here; only 4-wide state remains.

    // ---- encoder residual blocks ----
    lin<4, 4, true>(s, O_W_H2, O_B_H2, x, t);
    lin_add<4, 4>  (s, O_W_H3, O_B_H3, t, x);

    lin<4, 4, true>(s, O_W_H4, O_B_H4, x, t);
    lin_add<4, 4>  (s, O_W_H5, O_B_H5, t, x);

    // ---- encode (4 -> 1) ----
    u64 e[2][1];
    lin<4, 1, true>(s, O_W_EN, O_B_EN, x, e);

    // store x_encode (streaming)
#pragma unroll
    for (int p = 0; p < 2; p++) {
        unsigned rA = base + (2 * p) * NTH;
        unsigned rB = rA + NTH;
        float eA, eB;
        unpack2(e[p][0], eA, eB);
        if (rA < (unsigned)N) __stcs(out + rA, eA);
        if (rB < (unsigned)N) __stcs(out + rB, eB);
    }

    // ---- decoder ----
    lin<1, 4, true>(s, O_W_H6, O_B_H6, e, x);

    lin<4, 4, true>(s, O_W_H7, O_B_H7, x, t);
    lin_add<4, 4>  (s, O_W_H8, O_B_H8, t, x);

    lin<4, 4, true>(s, O_W_H9, O_B_H9, x, t);
    lin_add<4, 4>  (s, O_W_HA, O_B_HA, t, x);

    // ---- decode (4 -> 8) ----
    u64 d8[2][8];
    lin<4, 8, true>(s, O_W_DE, O_B_DE, x, d8);

    // store x_decode (streaming, two float4 per row)
    float* __restrict__ dec = out + N;
#pragma unroll
    for (int p = 0; p < 2; p++) {
        unsigned rA = base + (2 * p) * NTH;
        unsigned rB = rA + NTH;
        float a[8], b[8];
#pragma unroll
        for (int j = 0; j < 8; j++) unpack2(d8[p][j], a[j], b[j]);
        if (rA < (unsigned)N) {
            __stcs(reinterpret_cast<float4*>(dec + (size_t)rA * 8),
                   make_float4(a[0], a[1], a[2], a[3]));
            __stcs(reinterpret_cast<float4*>(dec + (size_t)rA * 8 + 4),
                   make_float4(a[4], a[5], a[6], a[7]));
        }
        if (rB < (unsigned)N) {
            __stcs(reinterpret_cast<float4*>(dec + (size_t)rB * 8),
                   make_float4(b[0], b[1], b[2], b[3]));
            __stcs(reinterpret_cast<float4*>(dec + (size_t)rB * 8 + 4),
                   make_float4(b[4], b[5], b[6], b[7]));
        }
    }
}

extern "C" void kernel_launch(void* const* d_in, const int* in_sizes, int n_in,
                              void* d_out, int out_size) {
    Params P;
    for (int k = 0; k < 27; k++) P.p[k] = (const float*)d_in[k];
    int N = in_sizes[0] / 8;                 // 4194304 rows
    int rows_per_block = 4 * NTH;            // 1024
    int blocks = (N + rows_per_block - 1) / rows_per_block;
    ann_fused_kernel<<<blocks, NTH>>>(P, (float*)d_out, N);
}

// round 7
// speedup vs baseline: 1.3601x; 1.3601x over previous
#include <cuda_runtime.h>

#define NTH  256
typedef unsigned long long u64;

struct Params { const float* p[27]; };

// ---------- packed f32x2 primitives (sm_103a) ----------
__device__ __forceinline__ u64 ffma2(u64 a, u64 b, u64 c) {
    u64 d; asm("fma.rn.f32x2 %0,%1,%2,%3;" : "=l"(d) : "l"(a), "l"(b), "l"(c)); return d;
}
__device__ __forceinline__ u64 fmul2(u64 a, u64 b) {
    u64 d; asm("mul.rn.f32x2 %0,%1,%2;" : "=l"(d) : "l"(a), "l"(b)); return d;
}
__device__ __forceinline__ u64 fadd2(u64 a, u64 b) {
    u64 d; asm("add.rn.f32x2 %0,%1,%2;" : "=l"(d) : "l"(a), "l"(b)); return d;
}
__device__ __forceinline__ u64 pack2(float lo, float hi) {
    u64 d; asm("mov.b64 %0,{%1,%2};" : "=l"(d) : "f"(lo), "f"(hi)); return d;
}
__device__ __forceinline__ void unpack2(u64 v, float& lo, float& hi) {
    asm("mov.b64 {%0,%1},%2;" : "=f"(lo), "=f"(hi) : "l"(v));
}
__device__ __forceinline__ u64 abs2(u64 v) {
    u64 d; asm("and.b64 %0,%1,0x7FFFFFFF7FFFFFFF;" : "=l"(d) : "l"(v)); return d;
}
// Packed branchless leaky-relu (slope 0.0025): rr(v)=0.50125*v+0.49875*|v|.
__device__ __forceinline__ u64 rr2(u64 v) {
    const u64 C1 = pack2(0.50125f, 0.50125f);
    const u64 C2 = pack2(0.49875f, 0.49875f);
    return ffma2(v, C1, fmul2(abs2(v), C2));
}

// ---------- shared weight offsets (u64 slots, each scalar duplicated) ----------
#define O_W_IN   0
#define O_B_IN   64
#define O_W_H1   72
#define O_B_H1   104
#define O_W_H2   108
#define O_B_H2   124
#define O_W_H3   128
#define O_B_H3   144
#define O_W_H4   148
#define O_B_H4   164
#define O_W_H5   168
#define O_B_H5   184
#define O_W_EN   188
#define O_B_EN   192
#define O_W_H6   193
#define O_B_H6   197
#define O_W_H7   201
#define O_B_H7   217
#define O_W_H8   221
#define O_B_H8   237
#define O_W_H9   241
#define O_B_H9   257
#define O_W_HA   261
#define O_B_HA   277
#define O_W_DE   281
#define O_B_DE   313
#define S_TOTAL  321

template<int FI, int FO, bool ACT>
__device__ __forceinline__ void lin(const u64* __restrict__ s, int Woff, int boff,
                                    const u64 (&src)[2][FI], u64 (&dst)[2][FO]) {
#pragma unroll
    for (int j = 0; j < FO; j++) {
        u64 b = s[boff + j];
        u64 a0 = b, a1 = b;
#pragma unroll
        for (int i = 0; i < FI; i++) {
            u64 w = s[Woff + i * FO + j];       // one LDS.64 feeds both pairs
            a0 = ffma2(src[0][i], w, a0);
            a1 = ffma2(src[1][i], w, a1);
        }
        dst[0][j] = ACT ? rr2(a0) : a0;
        dst[1][j] = ACT ? rr2(a1) : a1;
    }
}

template<int FI, int FO>
__device__ __forceinline__ void lin_add(const u64* __restrict__ s, int Woff, int boff,
                                        const u64 (&src)[2][FI], u64 (&dst)[2][FO]) {
#pragma unroll
    for (int j = 0; j < FO; j++) {
        u64 b = s[boff + j];
        u64 a0 = b, a1 = b;
#pragma unroll
        for (int i = 0; i < FI; i++) {
            u64 w = s[Woff + i * FO + j];
            a0 = ffma2(src[0][i], w, a0);
            a1 = ffma2(src[1][i], w, a1);
        }
        dst[0][j] = fadd2(dst[0][j], a0);
        dst[1][j] = fadd2(dst[1][j], a1);
    }
}

template<bool GUARD>
__global__ __launch_bounds__(NTH, 3)
void ann_fused_kernel(Params P, float* __restrict__ out, int N) {
    __shared__ u64 s[S_TOTAL];

    // Cooperative weight load: duplicate each scalar into both f32x2 lanes.
    {
        const int sz[26] = {64,8,32,4,16,4,16,4,16,4,16,4,4,1,4,4,16,4,16,4,16,4,16,4,32,8};
        int off = 0;
        for (int k = 0; k < 26; k++) {
            const float* src = P.p[k + 1];
            for (int i = threadIdx.x; i < sz[k]; i += NTH) {
                float v = src[i];
                s[off + i] = pack2(v, v);
            }
            off += sz[k];
        }
    }
    __syncthreads();

    const float* __restrict__ xin = P.p[0];
    unsigned base = blockIdx.x * (4 * NTH) + threadIdx.x;
    // pair p covers rows (base + 2p*NTH, base + (2p+1)*NTH)

    // ---- load x_in, pack 2 rows per u64 lane (streaming float4) ----
    u64 x8[2][8];
#pragma unroll
    for (int p = 0; p < 2; p++) {
        unsigned rA = base + (2 * p) * NTH;
        unsigned rB = rA + NTH;
        float4 a0, a1, b0, b1;
        if (!GUARD || rA < (unsigned)N) {
            a0 = __ldcs(reinterpret_cast<const float4*>(xin + (size_t)rA * 8));
            a1 = __ldcs(reinterpret_cast<const float4*>(xin + (size_t)rA * 8 + 4));
        } else { a0 = a1 = make_float4(0.f,0.f,0.f,0.f); }
        if (!GUARD || rB < (unsigned)N) {
            b0 = __ldcs(reinterpret_cast<const float4*>(xin + (size_t)rB * 8));
            b1 = __ldcs(reinterpret_cast<const float4*>(xin + (size_t)rB * 8 + 4));
        } else { b0 = b1 = make_float4(0.f,0.f,0.f,0.f); }
        x8[p][0] = pack2(a0.x, b0.x); x8[p][1] = pack2(a0.y, b0.y);
        x8[p][2] = pack2(a0.z, b0.z); x8[p][3] = pack2(a0.w, b0.w);
        x8[p][4] = pack2(a1.x, b1.x); x8[p][5] = pack2(a1.y, b1.y);
        x8[p][6] = pack2(a1.z, b1.z); x8[p][7] = pack2(a1.w, b1.w);
    }

    // ---- fused in+h1 (column-wise; x8 retired unit by unit, low liveness) ----
    u64 x[2][4], t[2][4];
#pragma unroll
    for (int k = 0; k < 4; k++) { u64 b = s[O_B_H1 + k]; x[0][k] = b; x[1][k] = b; }
#pragma unroll
    for (int j = 0; j < 8; j++) {
        u64 b = s[O_B_IN + j];
        u64 a0 = b, a1 = b;
#pragma unroll
        for (int i = 0; i < 8; i++) {
            u64 w = s[O_W_IN + i * 8 + j];
            a0 = ffma2(x8[0][i], w, a0);
            a1 = ffma2(x8[1][i], w, a1);
        }
        a0 = rr2(a0); a1 = rr2(a1);
#pragma unroll
        for (int k = 0; k < 4; k++) {
            u64 w = s[O_W_H1 + j * 4 + k];
            x[0][k] = ffma2(a0, w, x[0][k]);
            x[1][k] = ffma2(a1, w, x[1][k]);
        }
    }

    // ---- encoder residual blocks ----
    lin<4, 4, true>(s, O_W_H2, O_B_H2, x, t);
    lin_add<4, 4>  (s, O_W_H3, O_B_H3, t, x);

    lin<4, 4, true>(s, O_W_H4, O_B_H4, x, t);
    lin_add<4, 4>  (s, O_W_H5, O_B_H5, t, x);

    // ---- encode (4 -> 1) + store ----
    u64 e[2][1];
    lin<4, 1, true>(s, O_W_EN, O_B_EN, x, e);
#pragma unroll
    for (int p = 0; p < 2; p++) {
        unsigned rA = base + (2 * p) * NTH;
        unsigned rB = rA + NTH;
        float eA, eB;
        unpack2(e[p][0], eA, eB);
        if (!GUARD || rA < (unsigned)N) __stcs(out + rA, eA);
        if (!GUARD || rB < (unsigned)N) __stcs(out + rB, eB);
    }

    // ---- decoder ----
    lin<1, 4, true>(s, O_W_H6, O_B_H6, e, x);

    lin<4, 4, true>(s, O_W_H7, O_B_H7, x, t);
    lin_add<4, 4>  (s, O_W_H8, O_B_H8, t, x);

    lin<4, 4, true>(s, O_W_H9, O_B_H9, x, t);
    lin_add<4, 4>  (s, O_W_HA, O_B_HA, t, x);

    // ---- decode (4 -> 8), computed AND stored one pair at a time (low tail liveness) ----
    float* __restrict__ dec = out + N;
#pragma unroll
    for (int p = 0; p < 2; p++) {
        u64 d[8];
#pragma unroll
        for (int j = 0; j < 8; j++) {
            u64 a = s[O_B_DE + j];
#pragma unroll
            for (int i = 0; i < 4; i++)
                a = ffma2(x[p][i], s[O_W_DE + i * 8 + j], a);
            d[j] = rr2(a);
        }
        unsigned rA = base + (2 * p) * NTH;
        unsigned rB = rA + NTH;
        float a[8], b[8];
#pragma unroll
        for (int j = 0; j < 8; j++) unpack2(d[j], a[j], b[j]);
        if (!GUARD || rA < (unsigned)N) {
            __stcs(reinterpret_cast<float4*>(dec + (size_t)rA * 8),
                   make_float4(a[0], a[1], a[2], a[3]));
            __stcs(reinterpret_cast<float4*>(dec + (size_t)rA * 8 + 4),
                   make_float4(a[4], a[5], a[6], a[7]));
        }
        if (!GUARD || rB < (unsigned)N) {
            __stcs(reinterpret_cast<float4*>(dec + (size_t)rB * 8),
                   make_float4(b[0], b[1], b[2], b[3]));
            __stcs(reinterpret_cast<float4*>(dec + (size_t)rB * 8 + 4),
                   make_float4(b[4], b[5], b[6], b[7]));
        }
    }
}

extern "C" void kernel_launch(void* const* d_in, const int* in_sizes, int n_in,
                              void* d_out, int out_size) {
    Params P;
    for (int k = 0; k < 27; k++) P.p[k] = (const float*)d_in[k];
    int N = in_sizes[0] / 8;                 // 4194304 rows
    int rows_per_block = 4 * NTH;            // 1024
    int blocks = (N + rows_per_block - 1) / rows_per_block;
    if (N % rows_per_block == 0)
        ann_fused_kernel<false><<<blocks, NTH>>>(P, (float*)d_out, N);
    else
        ann_fused_kernel<true ><<<blocks, NTH>>>(P, (float*)d_out, N);
}

// round 8
// speedup vs baseline: 1.7650x; 1.2977x over previous
#include <cuda_runtime.h>

#define NTH  256

struct Params { const float* p[27]; };

// Exact leaky-relu slope 0.0025: rr(v) = max(v, 0.0025*v).
// v>=0: v >= 0.0025v -> v.  v<0: 0.0025v > v -> 0.0025v.
// FMUL (fma pipe) + FMNMX (alu pipe) — offloads the fma pipe, no predicates.
__device__ __forceinline__ float rr(float v) {
    return fmaxf(v, 0.0025f * v);
}

// ---- shared layout (floats); every W/b offset is 16B-aligned for LDS.128 ----
// W_in stored TRANSPOSED: s[j*8+i] = W_in[i][j]
#define O_WIN_T  0      // 64
#define O_B_IN   64     // 8
#define O_W_H1   72     // [8][4] row-major, 32
#define O_B_H1   104    // 4
#define O_W_H2   108
#define O_B_H2   124
#define O_W_H3   128
#define O_B_H3   144
#define O_W_H4   148
#define O_B_H4   164
#define O_W_H5   168
#define O_B_H5   184
#define O_W_EN   188    // 4 (column vector, contiguous)
#define O_B_EN   192    // 1 (+3 pad)
#define O_W_H6   196    // 4 ([1][4] row, contiguous)
#define O_B_H6   200    // 4
#define O_W_H7   204
#define O_B_H7   220
#define O_W_H8   224
#define O_B_H8   240
#define O_W_H9   244
#define O_B_H9   260
#define O_W_HA   264
#define O_B_HA   280
#define O_W_DE   284    // [4][8] row-major, 32
#define O_B_DE   316    // 8
#define S_TOTAL  324

__device__ __forceinline__ float4 ld4(const float* s, int off) {
    return *reinterpret_cast<const float4*>(s + off);
}

// 4x4 layer, j-vectorized: dst[r][:] = (ACT? rr:id)(b + src[r][:] @ W)
// 5 LDS.128 total (4 weight rows + bias).
template<bool ACT, bool RESID>
__device__ __forceinline__ void lin44(const float* __restrict__ s, int Woff, int boff,
                                      const float (&src)[4][4], float (&dst)[4][4]) {
    float4 b = ld4(s, boff);
    float acc[4][4];
#pragma unroll
    for (int r = 0; r < 4; r++) {
        acc[r][0] = b.x; acc[r][1] = b.y; acc[r][2] = b.z; acc[r][3] = b.w;
    }
#pragma unroll
    for (int i = 0; i < 4; i++) {
        float4 w = ld4(s, Woff + 4 * i);
#pragma unroll
        for (int r = 0; r < 4; r++) {
            acc[r][0] = fmaf(src[r][i], w.x, acc[r][0]);
            acc[r][1] = fmaf(src[r][i], w.y, acc[r][1]);
            acc[r][2] = fmaf(src[r][i], w.z, acc[r][2]);
            acc[r][3] = fmaf(src[r][i], w.w, acc[r][3]);
        }
    }
#pragma unroll
    for (int r = 0; r < 4; r++)
#pragma unroll
        for (int j = 0; j < 4; j++)
            dst[r][j] = RESID ? (dst[r][j] + acc[r][j]) : (ACT ? rr(acc[r][j]) : acc[r][j]);
}

template<bool GUARD>
__global__ __launch_bounds__(NTH, 4)
void ann_fused_kernel(Params P, float* __restrict__ out, int N) {
    __shared__ alignas(16) float s[S_TOTAL];

    // ---- cooperative weight staging (once per block) ----
    {
        // W_in transposed: s[j*8+i] = W_in[i*8+j]
        const float* win = P.p[1];
        for (int idx = threadIdx.x; idx < 64; idx += NTH) {
            int i = idx >> 3, j = idx & 7;
            s[O_WIN_T + j * 8 + i] = win[idx];
        }
        // remaining params: {d_in index, dst offset, count}
        const short off[25] = {O_B_IN,O_W_H1,O_B_H1,O_W_H2,O_B_H2,O_W_H3,O_B_H3,
                               O_W_H4,O_B_H4,O_W_H5,O_B_H5,O_W_EN,O_B_EN,O_W_H6,O_B_H6,
                               O_W_H7,O_B_H7,O_W_H8,O_B_H8,O_W_H9,O_B_H9,O_W_HA,O_B_HA,
                               O_W_DE,O_B_DE};
        const short cnt[25] = {8,32,4,16,4,16,4,16,4,16,4,4,1,4,4,16,4,16,4,16,4,16,4,32,8};
        for (int k = 0; k < 25; k++) {
            const float* src = P.p[k + 2];
            for (int i = threadIdx.x; i < cnt[k]; i += NTH) s[off[k] + i] = src[i];
        }
    }
    __syncthreads();

    const float* __restrict__ xin = P.p[0];
    unsigned base = blockIdx.x * (4 * NTH) + threadIdx.x;

    // ---- load 4 rows (streaming, coalesced float4) ----
    float x8[4][8];
#pragma unroll
    for (int r = 0; r < 4; r++) {
        unsigned row = base + r * NTH;
        if (!GUARD || row < (unsigned)N) {
            float4 a = __ldcs(reinterpret_cast<const float4*>(xin + (size_t)row * 8));
            float4 b = __ldcs(reinterpret_cast<const float4*>(xin + (size_t)row * 8 + 4));
            x8[r][0]=a.x; x8[r][1]=a.y; x8[r][2]=a.z; x8[r][3]=a.w;
            x8[r][4]=b.x; x8[r][5]=b.y; x8[r][6]=b.z; x8[r][7]=b.w;
        } else {
#pragma unroll
            for (int i = 0; i < 8; i++) x8[r][i] = 0.f;
        }
    }

    // ---- fused in+h1, column-wise over the 8 hidden units ----
    float x[4][4], t[4][4];
    {
        float4 bh1 = ld4(s, O_B_H1);
#pragma unroll
        for (int r = 0; r < 4; r++) {
            x[r][0]=bh1.x; x[r][1]=bh1.y; x[r][2]=bh1.z; x[r][3]=bh1.w;
        }
#pragma unroll
        for (int j = 0; j < 8; j++) {
            float bj = s[O_B_IN + j];
            float4 w0 = ld4(s, O_WIN_T + j * 8);
            float4 w1 = ld4(s, O_WIN_T + j * 8 + 4);
            float a[4];
#pragma unroll
            for (int r = 0; r < 4; r++) {
                float v = bj;
                v = fmaf(x8[r][0], w0.x, v); v = fmaf(x8[r][1], w0.y, v);
                v = fmaf(x8[r][2], w0.z, v); v = fmaf(x8[r][3], w0.w, v);
                v = fmaf(x8[r][4], w1.x, v); v = fmaf(x8[r][5], w1.y, v);
                v = fmaf(x8[r][6], w1.z, v); v = fmaf(x8[r][7], w1.w, v);
                a[r] = rr(v);
            }
            float4 h = ld4(s, O_W_H1 + j * 4);
#pragma unroll
            for (int r = 0; r < 4; r++) {
                x[r][0] = fmaf(a[r], h.x, x[r][0]);
                x[r][1] = fmaf(a[r], h.y, x[r][1]);
                x[r][2] = fmaf(a[r], h.z, x[r][2]);
                x[r][3] = fmaf(a[r], h.w, x[r][3]);
            }
        }
    }

    // ---- encoder residual blocks ----
    lin44<true,  false>(s, O_W_H2, O_B_H2, x, t);
    lin44<false, true >(s, O_W_H3, O_B_H3, t, x);
    lin44<true,  false>(s, O_W_H4, O_B_H4, x, t);
    lin44<false, true >(s, O_W_H5, O_B_H5, t, x);

    // ---- encode (4 -> 1) + store ----
    float e[4];
    {
        float4 we = ld4(s, O_W_EN);
        float be = s[O_B_EN];
#pragma unroll
        for (int r = 0; r < 4; r++) {
            float v = be;
            v = fmaf(x[r][0], we.x, v); v = fmaf(x[r][1], we.y, v);
            v = fmaf(x[r][2], we.z, v); v = fmaf(x[r][3], we.w, v);
            e[r] = rr(v);
        }
    }
#pragma unroll
    for (int r = 0; r < 4; r++) {
        unsigned row = base + r * NTH;
        if (!GUARD || row < (unsigned)N) __stcs(out + row, e[r]);
    }

    // ---- h6 (1 -> 4) ----
    {
        float4 w6 = ld4(s, O_W_H6);
        float4 b6 = ld4(s, O_B_H6);
#pragma unroll
        for (int r = 0; r < 4; r++) {
            x[r][0] = rr(fmaf(e[r], w6.x, b6.x));
            x[r][1] = rr(fmaf(e[r], w6.y, b6.y));
            x[r][2] = rr(fmaf(e[r], w6.z, b6.z));
            x[r][3] = rr(fmaf(e[r], w6.w, b6.w));
        }
    }

    // ---- decoder residual blocks ----
    lin44<true,  false>(s, O_W_H7, O_B_H7, x, t);
    lin44<false, true >(s, O_W_H8, O_B_H8, t, x);
    lin44<true,  false>(s, O_W_H9, O_B_H9, x, t);
    lin44<false, true >(s, O_W_HA, O_B_HA, t, x);

    // ---- decode (4 -> 8) + store, j-vectorized, 10 LDS.128 for all 4 rows ----
    float* __restrict__ dec = out + N;
    {
        float4 b0 = ld4(s, O_B_DE);
        float4 b1 = ld4(s, O_B_DE + 4);
        float d[4][8];
#pragma unroll
        for (int r = 0; r < 4; r++) {
            d[r][0]=b0.x; d[r][1]=b0.y; d[r][2]=b0.z; d[r][3]=b0.w;
            d[r][4]=b1.x; d[r][5]=b1.y; d[r][6]=b1.z; d[r][7]=b1.w;
        }
#pragma unroll
        for (int i = 0; i < 4; i++) {
            float4 w0 = ld4(s, O_W_DE + i * 8);
            float4 w1 = ld4(s, O_W_DE + i * 8 + 4);
#pragma unroll
            for (int r = 0; r < 4; r++) {
                d[r][0] = fmaf(x[r][i], w0.x, d[r][0]);
                d[r][1] = fmaf(x[r][i], w0.y, d[r][1]);
                d[r][2] = fmaf(x[r][i], w0.z, d[r][2]);
                d[r][3] = fmaf(x[r][i], w0.w, d[r][3]);
                d[r][4] = fmaf(x[r][i], w1.x, d[r][4]);
                d[r][5] = fmaf(x[r][i], w1.y, d[r][5]);
                d[r][6] = fmaf(x[r][i], w1.z, d[r][6]);
                d[r][7] = fmaf(x[r][i], w1.w, d[r][7]);
            }
        }
#pragma unroll
        for (int r = 0; r < 4; r++) {
            unsigned row = base + r * NTH;
            if (!GUARD || row < (unsigned)N) {
                __stcs(reinterpret_cast<float4*>(dec + (size_t)row * 8),
                       make_float4(rr(d[r][0]), rr(d[r][1]), rr(d[r][2]), rr(d[r][3])));
                __stcs(reinterpret_cast<float4*>(dec + (size_t)row * 8 + 4),
                       make_float4(rr(d[r][4]), rr(d[r][5]), rr(d[r][6]), rr(d[r][7])));
            }
        }
    }
}

extern "C" void kernel_launch(void* const* d_in, const int* in_sizes, int n_in,
                              void* d_out, int out_size) {
    Params P;
    for (int k = 0; k < 27; k++) P.p[k] = (const float*)d_in[k];
    int N = in_sizes[0] / 8;                 // 4194304 rows
    int rows_per_block = 4 * NTH;            // 1024
    int blocks = (N + rows_per_block - 1) / rows_per_block;
    if (N % rows_per_block == 0)
        ann_fused_kernel<false><<<blocks, NTH>>>(P, (float*)d_out, N);
    else
        ann_fused_kernel<true ><<<blocks, NTH>>>(P, (float*)d_out, N);
}